// round 16
// baseline (speedup 1.0000x reference)
#include <cuda_runtime.h>
#include <cuda_fp16.h>

#define B_      4
#define C_      128
#define N_      4096
#define HEADS_  4
#define DHEAD_  32
#define HID_    128
#define OQKV_   384

typedef unsigned int u32;

// Scratch (static device globals — no runtime allocation)
__device__ __half g_x2[B_ * N_ * 256];
__device__ __half g_o2[B_ * N_ * 256];
__device__ __half g_w2q[OQKV_ * 256];
__device__ __half g_w2o[HID_ * 256];
__device__ __half g_q2[B_ * HEADS_ * N_ * 32];
__device__ __half g_k2[B_ * HEADS_ * N_ * 32];
__device__ __half g_vh[B_ * HID_ * N_];

// ---------------------------------------------------------------------------
__device__ __forceinline__ void mma16816(float* c, const unsigned* a,
                                         unsigned b0, unsigned b1) {
    asm volatile(
        "mma.sync.aligned.m16n8k16.row.col.f32.f16.f16.f32 "
        "{%0,%1,%2,%3}, {%4,%5,%6,%7}, {%8,%9}, {%0,%1,%2,%3};\n"
        : "+f"(c[0]), "+f"(c[1]), "+f"(c[2]), "+f"(c[3])
        : "r"(a[0]), "r"(a[1]), "r"(a[2]), "r"(a[3]), "r"(b0), "r"(b1));
}
// fp16-accumulator MMA (double-rate on the legacy tensor pipe)
__device__ __forceinline__ void mma16816_h(unsigned* d, const unsigned* a,
                                           unsigned b0, unsigned b1) {
    asm volatile(
        "mma.sync.aligned.m16n8k16.row.col.f16.f16.f16.f16 "
        "{%0,%1}, {%2,%3,%4,%5}, {%6,%7}, {%0,%1};\n"
        : "+r"(d[0]), "+r"(d[1])
        : "r"(a[0]), "r"(a[1]), "r"(a[2]), "r"(a[3]), "r"(b0), "r"(b1));
}
__device__ __forceinline__ void mma16816_h_dc(unsigned* d, const unsigned* a,
                                              unsigned b0, unsigned b1) {
    asm volatile(
        "mma.sync.aligned.m16n8k16.row.col.f16.f16.f16.f16 "
        "{%0,%1}, {%2,%3,%4,%5}, {%6,%7}, {%8,%9};\n"
        : "=&r"(d[0]), "=&r"(d[1])
        : "r"(a[0]), "r"(a[1]), "r"(a[2]), "r"(a[3]), "r"(b0), "r"(b1),
          "r"(0u), "r"(0u));
}
__device__ __forceinline__ unsigned ex2_h2(unsigned x) {
    unsigned y;
    asm("ex2.approx.f16x2 %0, %1;" : "=r"(y) : "r"(x));
    return y;
}
__device__ __forceinline__ void cp_async16(u32 dst, const void* src) {
    asm volatile("cp.async.cg.shared.global [%0], [%1], 16;\n"
                 :: "r"(dst), "l"(src) : "memory");
}
__device__ __forceinline__ void cp_commit() {
    asm volatile("cp.async.commit_group;\n" ::: "memory");
}
__device__ __forceinline__ void cp_wait0() {
    asm volatile("cp.async.wait_group 0;\n" ::: "memory");
}
__device__ __forceinline__ u32 smem_u32(const void* p) {
    u32 a;
    asm("{ .reg .u64 t; cvta.to.shared.u64 t, %1; cvt.u32.u64 %0, t; }"
        : "=r"(a) : "l"(p));
    return a;
}
__device__ __forceinline__ void ldsm_x4(u32* r, u32 addr) {
    asm volatile("ldmatrix.sync.aligned.m8n8.x4.shared.b16 {%0,%1,%2,%3}, [%4];"
                 : "=r"(r[0]), "=r"(r[1]), "=r"(r[2]), "=r"(r[3]) : "r"(addr));
}

// ---------------------------------------------------------------------------
// Kernel 1: weights -> hi|lo fp16 rows (qscale*log2e baked into q rows)
// ---------------------------------------------------------------------------
__global__ void w_convert_kernel(const float* __restrict__ w_qkv,
                                 const float* __restrict__ w_out) {
    int row = blockIdx.x;
    int c   = threadIdx.x;
    const float* src;
    __half* dst;
    float scale = 1.0f;
    if (row < OQKV_) {
        src = w_qkv + (size_t)row * C_;
        dst = g_w2q + (size_t)row * 256;
        if (row < HID_)
            scale = 0.17677669529663687f * 1.4426950408889634f;  // 32^-.5 * log2e
    } else {
        src = w_out + (size_t)(row - OQKV_) * C_;
        dst = g_w2o + (size_t)(row - OQKV_) * 256;
    }
    float v = src[c] * scale;
    __half hh = __float2half_rn(v);
    dst[c]       = hh;
    dst[128 + c] = __float2half_rn(v - __half2float(hh));
}

// ---------------------------------------------------------------------------
// Kernel 2: fused LN stats + LN apply + transpose + hi/lo split
// ---------------------------------------------------------------------------
__global__ __launch_bounds__(256) void x_convert_kernel(
    const float* __restrict__ x,
    const float* __restrict__ gamma, const float* __restrict__ beta) {
    __shared__ float xs[128][33];
    __shared__ float ps[8][32], pq[8][32];
    __shared__ float mm[32], rs[32];

    int n0 = blockIdx.x * 32;
    int b  = blockIdx.y;
    int tid = threadIdx.x;

#pragma unroll
    for (int t = 0; t < 16; t++) {
        int idx = tid + t * 256;
        int c = idx >> 5, nn = idx & 31;
        xs[c][nn] = x[((size_t)b * C_ + c) * N_ + n0 + nn];
    }
    __syncthreads();

    {
        int nn = tid & 31, ch = tid >> 5;
        float s = 0.f, s2 = 0.f;
#pragma unroll
        for (int k = 0; k < 16; k++) {
            float v = xs[ch * 16 + k][nn];
            s += v; s2 += v * v;
        }
        ps[ch][nn] = s; pq[ch][nn] = s2;
    }
    __syncthreads();
    if (tid < 32) {
        float s = 0.f, s2 = 0.f;
#pragma unroll
        for (int ch = 0; ch < 8; ch++) { s += ps[ch][tid]; s2 += pq[ch][tid]; }
        float m = s * (1.0f / C_);
        mm[tid] = m;
        rs[tid] = rsqrtf(s2 * (1.0f / C_) - m * m + 1e-5f);
    }
    __syncthreads();

#pragma unroll
    for (int t = 0; t < 16; t++) {
        int idx = tid + t * 256;
        int nn = idx >> 7, c = idx & 127;
        float v = (xs[c][nn] - mm[nn]) * rs[nn] * gamma[c] + beta[c];
        __half hh = __float2half_rn(v);
        __half* base = g_x2 + ((size_t)(b * N_ + n0 + nn)) * 256;
        base[c]       = hh;
        base[128 + c] = __float2half_rn(v - __half2float(hh));
    }
}

// ---------------------------------------------------------------------------
// Tensor-core GEMM (hi/lo compensated), ldmatrix + cp.async + staged epilogues
// mode 0: q rows fp16  1: k rows fp16  2: v [d][n] fp16  3: fp32 out + bias
// ---------------------------------------------------------------------------
__global__ __launch_bounds__(256) void tc_gemm_kernel(
    float* __restrict__ outp, const float* __restrict__ bias, int mode_base) {
    __shared__ __align__(16) __half XS[2][64][136];

    int b  = blockIdx.z;
    int n0 = blockIdx.x * 64;
    int mode = mode_base + blockIdx.y;
    const __half* W  = (mode < 3) ? (g_w2q + (size_t)blockIdx.y * HID_ * 256) : g_w2o;
    const __half* Bb = ((mode < 3) ? g_x2 : g_o2) + ((size_t)(b * N_ + n0)) * 256;

    int tid = threadIdx.x;
    int wid = tid >> 5, lane = tid & 31;
    int lq = lane >> 2, lr = lane & 3;
    u32 sb = smem_u32(&XS[0][0][0]);

#pragma unroll
    for (int t = 0; t < 8; t++) {
        int idx = tid + t * 256;
        int row = idx >> 5, c16 = idx & 31;
        int hl = c16 >> 4, off = (c16 & 15) * 8;
        cp_async16(sb + (u32)(((hl * 64 + row) * 136 + off) * 2),
                   Bb + (size_t)row * 256 + c16 * 8);
    }
    cp_commit();
    cp_wait0();
    __syncthreads();

    float s[8][4] = {};
    int r0 = wid * 16 + lq;
    int lm = lane >> 3, lrow = lane & 7;

#pragma unroll
    for (int ks = 0; ks < 8; ks++) {
        unsigned ah[4], al[4];
#pragma unroll
        for (int f = 0; f < 4; f++) {
            int rr = r0 + ((f & 1) ? 8 : 0);
            int kk = ks * 16 + lr * 2 + ((f & 2) ? 8 : 0);
            ah[f] = *reinterpret_cast<const unsigned*>(W + (size_t)rr * 256 + kk);
            al[f] = *reinterpret_cast<const unsigned*>(W + (size_t)rr * 256 + kk + 128);
        }
#pragma unroll
        for (int p = 0; p < 4; p++) {
            int nt = 2 * p + (lm >> 1);
            u32 ah_addr = sb + (u32)((((nt * 8 + lrow)) * 136 + ks * 16 + (lm & 1) * 8) * 2);
            u32 bh[4], bl[4];
            ldsm_x4(bh, ah_addr);
            ldsm_x4(bl, ah_addr + 64 * 136 * 2);
            mma16816(s[2 * p],     ah, bh[0], bh[1]);
            mma16816(s[2 * p],     ah, bl[0], bl[1]);
            mma16816(s[2 * p],     al, bh[0], bh[1]);
            mma16816(s[2 * p + 1], ah, bh[2], bh[3]);
            mma16816(s[2 * p + 1], ah, bl[2], bl[3]);
            mma16816(s[2 * p + 1], al, bh[2], bh[3]);
        }
    }
    __syncthreads();

    __half* XE = &XS[0][0][0];
    if (mode <= 1) {
#pragma unroll
        for (int part = 0; part < 2; part++) {
            int rr = r0 + part * 8;
#pragma unroll
            for (int nt = 0; nt < 8; nt++) {
#pragma unroll
                for (int cc = 0; cc < 2; cc++) {
                    int n = nt * 8 + lr * 2 + cc;
                    XE[n * 136 + rr] = __float2half_rn(s[nt][part * 2 + cc]);
                }
            }
        }
        __syncthreads();
        __half* base = (mode == 0) ? g_q2 : g_k2;
#pragma unroll
        for (int t = 0; t < 4; t++) {
            int idx = tid + t * 256;
            int n = idx >> 4, h = (idx >> 2) & 3, c = idx & 3;
            uint4 v = *reinterpret_cast<const uint4*>(&XE[n * 136 + h * 32 + c * 8]);
            *reinterpret_cast<uint4*>(base +
                ((size_t)(b * HEADS_ + h) * N_ + n0 + n) * 32 + c * 8) = v;
        }
    } else if (mode == 2) {
#pragma unroll
        for (int part = 0; part < 2; part++) {
            int rr = r0 + part * 8;
#pragma unroll
            for (int nt = 0; nt < 8; nt++) {
#pragma unroll
                for (int cc = 0; cc < 2; cc++) {
                    int n = nt * 8 + lr * 2 + cc;
                    XE[rr * 72 + n] = __float2half_rn(s[nt][part * 2 + cc]);
                }
            }
        }
        __syncthreads();
#pragma unroll
        for (int t = 0; t < 4; t++) {
            int idx = tid + t * 256;
            int o = idx >> 3, c = idx & 7;
            uint4 v = *reinterpret_cast<const uint4*>(&XE[o * 72 + c * 8]);
            *reinterpret_cast<uint4*>(g_vh +
                (size_t)(b * HID_ + o) * N_ + n0 + c * 8) = v;
        }
    } else {
#pragma unroll
        for (int part = 0; part < 2; part++) {
            int r = r0 + part * 8;
            float bv = bias[r];
            float* dst = outp + ((size_t)(b * HID_ + r)) * N_;
#pragma unroll
            for (int nt = 0; nt < 8; nt++) {
#pragma unroll
                for (int cc = 0; cc < 2; cc++) {
                    int n = n0 + nt * 8 + lr * 2 + cc;
                    dst[n] = s[nt][part * 2 + cc] + bv;
                }
            }
        }
    }
}

// ---------------------------------------------------------------------------
// Flash attention, all-fp16-accum MMAs. L via FADD on exp'd P fragments
// (no ones-column MMA). Deferred O flush (hidden under next tile's S_a).
// 256 thr, 128 i-rows, j-tile 128 (32 iters), cp.async double buffer.
// ---------------------------------------------------------------------------
#define KPITCH 40
#define VPITCH 136
#define KBUFH  5120     // 128*40 halves
#define VBUFH  4352     // 32*136
#define BUFH   9472
#define ATTN_SMEM_BYTES (2 * BUFH * 2)   // 37888

__global__ __launch_bounds__(256, 4) void attn_mma_kernel() {
    extern __shared__ __align__(16) __half SM[];
    float* SMf = reinterpret_cast<float*>(SM);

    int bh = blockIdx.y;
    int b = bh >> 2, h = bh & 3;
    int i0 = blockIdx.x * 128;
    int tid  = threadIdx.x;
    int wid  = tid >> 5;
    int lane = tid & 31;
    int lq   = lane >> 2;
    int lr   = lane & 3;
    int lm   = lane >> 3, lrow = lane & 7;

    const __half* qg = g_q2 + ((size_t)(b * HEADS_ + h) * N_ + i0) * 32;
    const __half* kg = g_k2 + (size_t)(b * HEADS_ + h) * N_ * 32;
    const __half* vg = g_vh + ((size_t)b * HID_ + h * DHEAD_) * N_;

    u32 sbase = smem_u32(SM);

    // ---- Q fragments straight from gmem ------------------------------------
    unsigned aQ[2][4];
    {
        int r0 = wid * 16 + lq;
#pragma unroll
        for (int kt = 0; kt < 2; kt++) {
#pragma unroll
            for (int f = 0; f < 4; f++) {
                int r = r0 + ((f & 1) ? 8 : 0);
                int d = kt * 16 + lr * 2 + ((f & 2) ? 8 : 0);
                aQ[kt][f] = *reinterpret_cast<const unsigned*>(qg + (size_t)r * 32 + d);
            }
        }
    }

    // ---- prefetch tile 0 ----------------------------------------------------
#pragma unroll
    for (int t = 0; t < 4; t++) {
        int idx = tid + t * 256;
        if (idx < 512) {
            int j = idx >> 2, c = idx & 3;
            cp_async16(sbase + (u32)((j * KPITCH + c * 8) * 2),
                       kg + (size_t)j * 32 + c * 8);
        } else {
            int i2 = idx - 512;
            int d = i2 >> 4, c = i2 & 15;
            cp_async16(sbase + (u32)((KBUFH + d * VPITCH + c * 8) * 2),
                       vg + (size_t)d * N_ + c * 8);
        }
    }
    cp_commit();

    unsigned sa[8][2], sb16[8][2];                  // f16x2 S accum / P frags
    float o[4][4] = {};                             // fp32 O accumulator
    unsigned o16[4][2];                             // per-tile fp16 O accum
    float L0 = 0.f, L1 = 0.f;
    const unsigned FULL = 0xffffffffu;

    for (int t128 = 0; t128 < 32; t128++) {
        int kb = (t128 & 1) * BUFH;
        int vb = kb + KBUFH;

        cp_wait0();
        __syncthreads();

        if (t128 < 31) {
            int j0n = (t128 + 1) * 128;
            u32 kdst = sbase + (u32)((BUFH - kb) * 2);
            u32 vdst = kdst + KBUFH * 2;
#pragma unroll
            for (int t = 0; t < 4; t++) {
                int idx = tid + t * 256;
                if (idx < 512) {
                    int j = idx >> 2, c = idx & 3;
                    cp_async16(kdst + (u32)((j * KPITCH + c * 8) * 2),
                               kg + (size_t)(j0n + j) * 32 + c * 8);
                } else {
                    int i2 = idx - 512;
                    int d = i2 >> 4, c = i2 & 15;
                    cp_async16(vdst + (u32)((d * VPITCH + c * 8) * 2),
                               vg + (size_t)d * N_ + j0n + c * 8);
                }
            }
            cp_commit();
        }

        // ---- S_a: j 0..63 (p 0..3), f16 accum chained over kt --------------
#pragma unroll
        for (int kt = 0; kt < 2; kt++) {
            int coff = kt * 16 + (lm & 1) * 8;
#pragma unroll
            for (int p = 0; p < 4; p++) {
                int ntb = 2 * p + (lm >> 1);
                u32 addr = sbase + (u32)((kb + (ntb * 8 + lrow) * KPITCH + coff) * 2);
                u32 bf[4];
                ldsm_x4(bf, addr);
                if (kt == 0) {
                    mma16816_h_dc(sa[2 * p],     aQ[0], bf[0], bf[1]);
                    mma16816_h_dc(sa[2 * p + 1], aQ[0], bf[2], bf[3]);
                } else {
                    mma16816_h(sa[2 * p],     aQ[1], bf[0], bf[1]);
                    mma16816_h(sa[2 * p + 1], aQ[1], bf[2], bf[3]);
                }
            }
        }

        // ---- deferred flush of PREVIOUS tile's o16 (hidden under S_a) ------
        if (t128 > 0) {
#pragma unroll
            for (int nt = 0; nt < 4; nt++) {
                float2 f0 = __half22float2(*reinterpret_cast<__half2*>(&o16[nt][0]));
                float2 f1 = __half22float2(*reinterpret_cast<__half2*>(&o16[nt][1]));
                o[nt][0] += f0.x; o[nt][1] += f0.y;
                o[nt][2] += f1.x; o[nt][3] += f1.y;
            }
        }

        // ---- exp_a ----------------------------------------------------------
#pragma unroll
        for (int nt = 0; nt < 8; nt++) {
            sa[nt][0] = ex2_h2(sa[nt][0]);
            sa[nt][1] = ex2_h2(sa[nt][1]);
        }

        // ---- S_b: j 64..127 (p 4..7) ---------------------------------------
#pragma unroll
        for (int kt = 0; kt < 2; kt++) {
            int coff = kt * 16 + (lm & 1) * 8;
#pragma unroll
            for (int p = 0; p < 4; p++) {
                int ntb = 2 * (p + 4) + (lm >> 1);
                u32 addr = sbase + (u32)((kb + (ntb * 8 + lrow) * KPITCH + coff) * 2);
                u32 bf[4];
                ldsm_x4(bf, addr);
                if (kt == 0) {
                    mma16816_h_dc(sb16[2 * p],     aQ[0], bf[0], bf[1]);
                    mma16816_h_dc(sb16[2 * p + 1], aQ[0], bf[2], bf[3]);
                } else {
                    mma16816_h(sb16[2 * p],     aQ[1], bf[0], bf[1]);
                    mma16816_h(sb16[2 * p + 1], aQ[1], bf[2], bf[3]);
                }
            }
        }

        // ---- PV_a: kt 0..3 consume sa; L via HADD2+FADD --------------------
#pragma unroll
        for (int kt = 0; kt < 4; kt++) {
            const unsigned* aP = &sa[2 * kt][0];
            int coff = kt * 16 + (lm & 1) * 8;
#pragma unroll
            for (int p = 0; p < 2; p++) {
                int ntb = 2 * p + (lm >> 1);
                u32 addr = sbase + (u32)((vb + (ntb * 8 + lrow) * VPITCH + coff) * 2);
                u32 bf[4];
                ldsm_x4(bf, addr);
                if (kt == 0) {
                    mma16816_h_dc(o16[2 * p],     aP, bf[0], bf[1]);
                    mma16816_h_dc(o16[2 * p + 1], aP, bf[2], bf[3]);
                } else {
                    mma16816_h(o16[2 * p],     aP, bf[0], bf[1]);
                    mma16816_h(o16[2 * p + 1], aP, bf[2], bf[3]);
                }
            }
            {   // row r partial: aP[0](k0,k1) + aP[2](k8,k9); row r+8: aP[1]+aP[3]
                __half2 h0 = __hadd2(*reinterpret_cast<const __half2*>(&aP[0]),
                                     *reinterpret_cast<const __half2*>(&aP[2]));
                __half2 h1 = __hadd2(*reinterpret_cast<const __half2*>(&aP[1]),
                                     *reinterpret_cast<const __half2*>(&aP[3]));
                float2 f0 = __half22float2(h0); L0 += f0.x + f0.y;
                float2 f1 = __half22float2(h1); L1 += f1.x + f1.y;
            }
        }

        // ---- exp_b ----------------------------------------------------------
#pragma unroll
        for (int nt = 0; nt < 8; nt++) {
            sb16[nt][0] = ex2_h2(sb16[nt][0]);
            sb16[nt][1] = ex2_h2(sb16[nt][1]);
        }

        // ---- PV_b: kt 4..7 consume sb16 ------------------------------------
#pragma unroll
        for (int kt = 4; kt < 8; kt++) {
            const unsigned* aP = &sb16[2 * (kt - 4)][0];
            int coff = kt * 16 + (lm & 1) * 8;
#pragma unroll
            for (int p = 0; p < 2; p++) {
                int ntb = 2 * p + (lm >> 1);
                u32 addr = sbase + (u32)((vb + (ntb * 8 + lrow) * VPITCH + coff) * 2);
                u32 bf[4];
                ldsm_x4(bf, addr);
                mma16816_h(o16[2 * p],     aP, bf[0], bf[1]);
                mma16816_h(o16[2 * p + 1], aP, bf[2], bf[3]);
            }
            {
                __half2 h0 = __hadd2(*reinterpret_cast<const __half2*>(&aP[0]),
                                     *reinterpret_cast<const __half2*>(&aP[2]));
                __half2 h1 = __hadd2(*reinterpret_cast<const __half2*>(&aP[1]),
                                     *reinterpret_cast<const __half2*>(&aP[3]));
                float2 f0 = __half22float2(h0); L0 += f0.x + f0.y;
                float2 f1 = __half22float2(h1); L1 += f1.x + f1.y;
            }
        }
    }

    // ---- final flush of last tile's o16 ------------------------------------
#pragma unroll
    for (int nt = 0; nt < 4; nt++) {
        float2 f0 = __half22float2(*reinterpret_cast<__half2*>(&o16[nt][0]));
        float2 f1 = __half22float2(*reinterpret_cast<__half2*>(&o16[nt][1]));
        o[nt][0] += f0.x; o[nt][1] += f0.y;
        o[nt][2] += f1.x; o[nt][3] += f1.y;
    }

    // ---- L quad reduction (across lr lanes) --------------------------------
    L0 += __shfl_xor_sync(FULL, L0, 1);
    L0 += __shfl_xor_sync(FULL, L0, 2);
    L1 += __shfl_xor_sync(FULL, L1, 1);
    L1 += __shfl_xor_sync(FULL, L1, 2);
    float inv0 = 1.0f / L0, inv1 = 1.0f / L1;

    // ---- epilogue: normalize, stage, write hi|lo rows into g_o2 ------------
    __syncthreads();
    {
        int r0 = wid * 16 + lq;
#pragma unroll
        for (int nt = 0; nt < 4; nt++) {
            int d = nt * 8 + lr * 2;
            SMf[r0 * 33 + d]           = o[nt][0] * inv0;
            SMf[r0 * 33 + d + 1]       = o[nt][1] * inv0;
            SMf[(r0 + 8) * 33 + d]     = o[nt][2] * inv1;
            SMf[(r0 + 8) * 33 + d + 1] = o[nt][3] * inv1;
        }
    }
    __syncthreads();
#pragma unroll
    for (int t = 0; t < 16; t++) {
        int idx = tid + t * 256;
        int i = idx >> 5, d = idx & 31;
        float v = SMf[i * 33 + d];
        __half hh = __float2half_rn(v);
        __half* rowp = g_o2 + ((size_t)(b * N_ + i0 + i)) * 256 + h * DHEAD_ + d;
        rowp[0]   = hh;
        rowp[128] = __float2half_rn(v - __half2float(hh));
    }
}

// ---------------------------------------------------------------------------
extern "C" void kernel_launch(void* const* d_in, const int* in_sizes, int n_in,
                              void* d_out, int out_size) {
    const float* x     = (const float*)d_in[0];
    const float* g     = (const float*)d_in[1];
    const float* beta  = (const float*)d_in[2];
    const float* w_qkv = (const float*)d_in[3];
    const float* w_out = (const float*)d_in[4];
    const float* b_out = (const float*)d_in[5];
    float* out = (float*)d_out;

    static int configured = 0;
    if (!configured) {
        cudaFuncSetAttribute(attn_mma_kernel,
                             cudaFuncAttributeMaxDynamicSharedMemorySize,
                             ATTN_SMEM_BYTES);
        cudaFuncSetAttribute(attn_mma_kernel,
                             cudaFuncAttributePreferredSharedMemoryCarveout,
                             100);
        configured = 1;
    }

    w_convert_kernel<<<OQKV_ + HID_, 128>>>(w_qkv, w_out);

    dim3 gx(N_ / 32, B_);
    x_convert_kernel<<<gx, 256>>>(x, g, beta);

    dim3 gq(N_ / 64, 3, B_);
    tc_gemm_kernel<<<gq, 256>>>(nullptr, nullptr, 0);

    dim3 ga(N_ / 128, B_ * HEADS_);
    attn_mma_kernel<<<ga, 256, ATTN_SMEM_BYTES>>>();

    dim3 go(N_ / 64, 1, B_);
    tc_gemm_kernel<<<go, 256>>>(out, b_out, 3);
}

// round 17
// speedup vs baseline: 1.0785x; 1.0785x over previous
#include <cuda_runtime.h>
#include <cuda_fp16.h>

#define B_      4
#define C_      128
#define N_      4096
#define HEADS_  4
#define DHEAD_  32
#define HID_    128
#define OQKV_   384

typedef unsigned int u32;

// Scratch (static device globals — no runtime allocation)
__device__ __half g_x2[B_ * N_ * 256];
__device__ __half g_o2[B_ * N_ * 256];
__device__ __half g_w2q[OQKV_ * 256];
__device__ __half g_w2o[HID_ * 256];
__device__ __half g_q2[B_ * HEADS_ * N_ * 32];
__device__ __half g_k2[B_ * HEADS_ * N_ * 32];
__device__ __half g_vh[B_ * HID_ * N_];

// ---------------------------------------------------------------------------
__device__ __forceinline__ void mma16816(float* c, const unsigned* a,
                                         unsigned b0, unsigned b1) {
    asm volatile(
        "mma.sync.aligned.m16n8k16.row.col.f32.f16.f16.f32 "
        "{%0,%1,%2,%3}, {%4,%5,%6,%7}, {%8,%9}, {%0,%1,%2,%3};\n"
        : "+f"(c[0]), "+f"(c[1]), "+f"(c[2]), "+f"(c[3])
        : "r"(a[0]), "r"(a[1]), "r"(a[2]), "r"(a[3]), "r"(b0), "r"(b1));
}
// fp16-accumulator MMA (double-rate on the legacy tensor pipe)
__device__ __forceinline__ void mma16816_h(unsigned* d, const unsigned* a,
                                           unsigned b0, unsigned b1) {
    asm volatile(
        "mma.sync.aligned.m16n8k16.row.col.f16.f16.f16.f16 "
        "{%0,%1}, {%2,%3,%4,%5}, {%6,%7}, {%0,%1};\n"
        : "+r"(d[0]), "+r"(d[1])
        : "r"(a[0]), "r"(a[1]), "r"(a[2]), "r"(a[3]), "r"(b0), "r"(b1));
}
__device__ __forceinline__ void mma16816_h_dc(unsigned* d, const unsigned* a,
                                              unsigned b0, unsigned b1) {
    asm volatile(
        "mma.sync.aligned.m16n8k16.row.col.f16.f16.f16.f16 "
        "{%0,%1}, {%2,%3,%4,%5}, {%6,%7}, {%8,%9};\n"
        : "=&r"(d[0]), "=&r"(d[1])
        : "r"(a[0]), "r"(a[1]), "r"(a[2]), "r"(a[3]), "r"(b0), "r"(b1),
          "r"(0u), "r"(0u));
}
__device__ __forceinline__ unsigned ex2_h2(unsigned x) {
    unsigned y;
    asm("ex2.approx.f16x2 %0, %1;" : "=r"(y) : "r"(x));
    return y;
}
__device__ __forceinline__ void cp_async16(u32 dst, const void* src) {
    asm volatile("cp.async.cg.shared.global [%0], [%1], 16;\n"
                 :: "r"(dst), "l"(src) : "memory");
}
__device__ __forceinline__ void cp_commit() {
    asm volatile("cp.async.commit_group;\n" ::: "memory");
}
__device__ __forceinline__ void cp_wait0() {
    asm volatile("cp.async.wait_group 0;\n" ::: "memory");
}
__device__ __forceinline__ u32 smem_u32(const void* p) {
    u32 a;
    asm("{ .reg .u64 t; cvta.to.shared.u64 t, %1; cvt.u32.u64 %0, t; }"
        : "=r"(a) : "l"(p));
    return a;
}
__device__ __forceinline__ void ldsm_x4(u32* r, u32 addr) {
    asm volatile("ldmatrix.sync.aligned.m8n8.x4.shared.b16 {%0,%1,%2,%3}, [%4];"
                 : "=r"(r[0]), "=r"(r[1]), "=r"(r[2]), "=r"(r[3]) : "r"(addr));
}

// ---------------------------------------------------------------------------
// Kernel 1: weights -> hi|lo fp16 rows (qscale*log2e baked into q rows)
// ---------------------------------------------------------------------------
__global__ void w_convert_kernel(const float* __restrict__ w_qkv,
                                 const float* __restrict__ w_out) {
    int row = blockIdx.x;
    int c   = threadIdx.x;
    const float* src;
    __half* dst;
    float scale = 1.0f;
    if (row < OQKV_) {
        src = w_qkv + (size_t)row * C_;
        dst = g_w2q + (size_t)row * 256;
        if (row < HID_)
            scale = 0.17677669529663687f * 1.4426950408889634f;  // 32^-.5 * log2e
    } else {
        src = w_out + (size_t)(row - OQKV_) * C_;
        dst = g_w2o + (size_t)(row - OQKV_) * 256;
    }
    float v = src[c] * scale;
    __half hh = __float2half_rn(v);
    dst[c]       = hh;
    dst[128 + c] = __float2half_rn(v - __half2float(hh));
}

// ---------------------------------------------------------------------------
// Kernel 2: fused LN stats + LN apply + transpose + hi/lo split
// ---------------------------------------------------------------------------
__global__ __launch_bounds__(256) void x_convert_kernel(
    const float* __restrict__ x,
    const float* __restrict__ gamma, const float* __restrict__ beta) {
    __shared__ float xs[128][33];
    __shared__ float ps[8][32], pq[8][32];
    __shared__ float mm[32], rs[32];

    int n0 = blockIdx.x * 32;
    int b  = blockIdx.y;
    int tid = threadIdx.x;

#pragma unroll
    for (int t = 0; t < 16; t++) {
        int idx = tid + t * 256;
        int c = idx >> 5, nn = idx & 31;
        xs[c][nn] = x[((size_t)b * C_ + c) * N_ + n0 + nn];
    }
    __syncthreads();

    {
        int nn = tid & 31, ch = tid >> 5;
        float s = 0.f, s2 = 0.f;
#pragma unroll
        for (int k = 0; k < 16; k++) {
            float v = xs[ch * 16 + k][nn];
            s += v; s2 += v * v;
        }
        ps[ch][nn] = s; pq[ch][nn] = s2;
    }
    __syncthreads();
    if (tid < 32) {
        float s = 0.f, s2 = 0.f;
#pragma unroll
        for (int ch = 0; ch < 8; ch++) { s += ps[ch][tid]; s2 += pq[ch][tid]; }
        float m = s * (1.0f / C_);
        mm[tid] = m;
        rs[tid] = rsqrtf(s2 * (1.0f / C_) - m * m + 1e-5f);
    }
    __syncthreads();

#pragma unroll
    for (int t = 0; t < 16; t++) {
        int idx = tid + t * 256;
        int nn = idx >> 7, c = idx & 127;
        float v = (xs[c][nn] - mm[nn]) * rs[nn] * gamma[c] + beta[c];
        __half hh = __float2half_rn(v);
        __half* base = g_x2 + ((size_t)(b * N_ + n0 + nn)) * 256;
        base[c]       = hh;
        base[128 + c] = __float2half_rn(v - __half2float(hh));
    }
}

// ---------------------------------------------------------------------------
// Tensor-core GEMM. mode 3 (fp32 out): full hi/lo 3-MMA compensation.
// modes 0-2 (q/k/v -> fp16): FAST single-MMA path (outputs are fp16 anyway),
// stages only hi rows, halves LDSM + cp.async traffic, 1/3 tensor work.
// ---------------------------------------------------------------------------
__global__ __launch_bounds__(256) void tc_gemm_kernel(
    float* __restrict__ outp, const float* __restrict__ bias, int mode_base) {
    __shared__ __align__(16) __half XS[2][64][136];

    int b  = blockIdx.z;
    int n0 = blockIdx.x * 64;
    int mode = mode_base + blockIdx.y;
    bool precise = (mode == 3);
    const __half* W  = (mode < 3) ? (g_w2q + (size_t)blockIdx.y * HID_ * 256) : g_w2o;
    const __half* Bb = ((mode < 3) ? g_x2 : g_o2) + ((size_t)(b * N_ + n0)) * 256;

    int tid = threadIdx.x;
    int wid = tid >> 5, lane = tid & 31;
    int lq = lane >> 2, lr = lane & 3;
    u32 sb = smem_u32(&XS[0][0][0]);

    if (precise) {
#pragma unroll
        for (int t = 0; t < 8; t++) {
            int idx = tid + t * 256;
            int row = idx >> 5, c16 = idx & 31;
            int hl = c16 >> 4, off = (c16 & 15) * 8;
            cp_async16(sb + (u32)(((hl * 64 + row) * 136 + off) * 2),
                       Bb + (size_t)row * 256 + c16 * 8);
        }
    } else {
#pragma unroll
        for (int t = 0; t < 4; t++) {
            int idx = tid + t * 256;
            int row = idx >> 4, c16 = idx & 15;
            cp_async16(sb + (u32)((row * 136 + c16 * 8) * 2),
                       Bb + (size_t)row * 256 + c16 * 8);
        }
    }
    cp_commit();
    cp_wait0();
    __syncthreads();

    float s[8][4] = {};
    int r0 = wid * 16 + lq;
    int lm = lane >> 3, lrow = lane & 7;

#pragma unroll
    for (int ks = 0; ks < 8; ks++) {
        unsigned ah[4], al[4];
#pragma unroll
        for (int f = 0; f < 4; f++) {
            int rr = r0 + ((f & 1) ? 8 : 0);
            int kk = ks * 16 + lr * 2 + ((f & 2) ? 8 : 0);
            ah[f] = *reinterpret_cast<const unsigned*>(W + (size_t)rr * 256 + kk);
            if (precise)
                al[f] = *reinterpret_cast<const unsigned*>(W + (size_t)rr * 256 + kk + 128);
        }
#pragma unroll
        for (int p = 0; p < 4; p++) {
            int nt = 2 * p + (lm >> 1);
            u32 ah_addr = sb + (u32)((((nt * 8 + lrow)) * 136 + ks * 16 + (lm & 1) * 8) * 2);
            u32 bh[4];
            ldsm_x4(bh, ah_addr);
            if (precise) {
                u32 bl[4];
                ldsm_x4(bl, ah_addr + 64 * 136 * 2);
                mma16816(s[2 * p],     ah, bh[0], bh[1]);
                mma16816(s[2 * p],     ah, bl[0], bl[1]);
                mma16816(s[2 * p],     al, bh[0], bh[1]);
                mma16816(s[2 * p + 1], ah, bh[2], bh[3]);
                mma16816(s[2 * p + 1], ah, bl[2], bl[3]);
                mma16816(s[2 * p + 1], al, bh[2], bh[3]);
            } else {
                mma16816(s[2 * p],     ah, bh[0], bh[1]);
                mma16816(s[2 * p + 1], ah, bh[2], bh[3]);
            }
        }
    }
    __syncthreads();

    __half* XE = &XS[0][0][0];
    if (mode <= 1) {
#pragma unroll
        for (int part = 0; part < 2; part++) {
            int rr = r0 + part * 8;
#pragma unroll
            for (int nt = 0; nt < 8; nt++) {
#pragma unroll
                for (int cc = 0; cc < 2; cc++) {
                    int n = nt * 8 + lr * 2 + cc;
                    XE[n * 136 + rr] = __float2half_rn(s[nt][part * 2 + cc]);
                }
            }
        }
        __syncthreads();
        __half* base = (mode == 0) ? g_q2 : g_k2;
#pragma unroll
        for (int t = 0; t < 4; t++) {
            int idx = tid + t * 256;
            int n = idx >> 4, h = (idx >> 2) & 3, c = idx & 3;
            uint4 v = *reinterpret_cast<const uint4*>(&XE[n * 136 + h * 32 + c * 8]);
            *reinterpret_cast<uint4*>(base +
                ((size_t)(b * HEADS_ + h) * N_ + n0 + n) * 32 + c * 8) = v;
        }
    } else if (mode == 2) {
#pragma unroll
        for (int part = 0; part < 2; part++) {
            int rr = r0 + part * 8;
#pragma unroll
            for (int nt = 0; nt < 8; nt++) {
#pragma unroll
                for (int cc = 0; cc < 2; cc++) {
                    int n = nt * 8 + lr * 2 + cc;
                    XE[rr * 72 + n] = __float2half_rn(s[nt][part * 2 + cc]);
                }
            }
        }
        __syncthreads();
#pragma unroll
        for (int t = 0; t < 4; t++) {
            int idx = tid + t * 256;
            int o = idx >> 3, c = idx & 7;
            uint4 v = *reinterpret_cast<const uint4*>(&XE[o * 72 + c * 8]);
            *reinterpret_cast<uint4*>(g_vh +
                (size_t)(b * HID_ + o) * N_ + n0 + c * 8) = v;
        }
    } else {
#pragma unroll
        for (int part = 0; part < 2; part++) {
            int r = r0 + part * 8;
            float bv = bias[r];
            float* dst = outp + ((size_t)(b * HID_ + r)) * N_;
#pragma unroll
            for (int nt = 0; nt < 8; nt++) {
#pragma unroll
                for (int cc = 0; cc < 2; cc++) {
                    int n = n0 + nt * 8 + lr * 2 + cc;
                    dst[n] = s[nt][part * 2 + cc] + bv;
                }
            }
        }
    }
}

// ---------------------------------------------------------------------------
// Flash attention (R13 winner): all-fp16-accum MMAs, phase-split halves,
// ones-column MMA for L. 256 thr, 128 i-rows, j-tile 128, cp.async dbuf.
// ---------------------------------------------------------------------------
#define KPITCH 40
#define VPITCH 136
#define KBUFH  5120     // 128*40 halves
#define VBUFH  4352     // 32*136
#define BUFH   9472

__global__ __launch_bounds__(256) void attn_mma_kernel() {
    __shared__ __align__(16) __half SM[2 * BUFH];   // 37888 B
    float* SMf = reinterpret_cast<float*>(SM);

    int bh = blockIdx.y;
    int b = bh >> 2, h = bh & 3;
    int i0 = blockIdx.x * 128;
    int tid  = threadIdx.x;
    int wid  = tid >> 5;
    int lane = tid & 31;
    int lq   = lane >> 2;
    int lr   = lane & 3;
    int lm   = lane >> 3, lrow = lane & 7;

    const __half* qg = g_q2 + ((size_t)(b * HEADS_ + h) * N_ + i0) * 32;
    const __half* kg = g_k2 + (size_t)(b * HEADS_ + h) * N_ * 32;
    const __half* vg = g_vh + ((size_t)b * HID_ + h * DHEAD_) * N_;

    u32 sbase = smem_u32(SM);

    // ---- Q fragments straight from gmem ------------------------------------
    unsigned aQ[2][4];
    {
        int r0 = wid * 16 + lq;
#pragma unroll
        for (int kt = 0; kt < 2; kt++) {
#pragma unroll
            for (int f = 0; f < 4; f++) {
                int r = r0 + ((f & 1) ? 8 : 0);
                int d = kt * 16 + lr * 2 + ((f & 2) ? 8 : 0);
                aQ[kt][f] = *reinterpret_cast<const unsigned*>(qg + (size_t)r * 32 + d);
            }
        }
    }

    // ---- prefetch tile 0 ----------------------------------------------------
#pragma unroll
    for (int t = 0; t < 4; t++) {
        int idx = tid + t * 256;
        if (idx < 512) {
            int j = idx >> 2, c = idx & 3;
            cp_async16(sbase + (u32)((j * KPITCH + c * 8) * 2),
                       kg + (size_t)j * 32 + c * 8);
        } else {
            int i2 = idx - 512;
            int d = i2 >> 4, c = i2 & 15;
            cp_async16(sbase + (u32)((KBUFH + d * VPITCH + c * 8) * 2),
                       vg + (size_t)d * N_ + c * 8);
        }
    }
    cp_commit();

    unsigned sa[8][2], sb16[8][2];                  // f16x2 S accum / P frags
    float o[4][4] = {};                             // fp32 O accumulator
    unsigned o16[4][2];                             // per-tile fp16 O accum
    unsigned L16[2];                                // per-tile fp16 L accum
    float L0 = 0.f, L1 = 0.f;
    const unsigned vone = (lq == 0) ? 0x3C003C00u : 0u;
    const unsigned FULL = 0xffffffffu;

    for (int t128 = 0; t128 < 32; t128++) {
        int kb = (t128 & 1) * BUFH;
        int vb = kb + KBUFH;

        cp_wait0();
        __syncthreads();

        if (t128 < 31) {
            int j0n = (t128 + 1) * 128;
            u32 kdst = sbase + (u32)((BUFH - kb) * 2);
            u32 vdst = kdst + KBUFH * 2;
#pragma unroll
            for (int t = 0; t < 4; t++) {
                int idx = tid + t * 256;
                if (idx < 512) {
                    int j = idx >> 2, c = idx & 3;
                    cp_async16(kdst + (u32)((j * KPITCH + c * 8) * 2),
                               kg + (size_t)(j0n + j) * 32 + c * 8);
                } else {
                    int i2 = idx - 512;
                    int d = i2 >> 4, c = i2 & 15;
                    cp_async16(vdst + (u32)((d * VPITCH + c * 8) * 2),
                               vg + (size_t)d * N_ + j0n + c * 8);
                }
            }
            cp_commit();
        }

        // ---- S_a: j 0..63 (p 0..3), f16 accum chained over kt --------------
#pragma unroll
        for (int kt = 0; kt < 2; kt++) {
            int coff = kt * 16 + (lm & 1) * 8;
#pragma unroll
            for (int p = 0; p < 4; p++) {
                int ntb = 2 * p + (lm >> 1);
                u32 addr = sbase + (u32)((kb + (ntb * 8 + lrow) * KPITCH + coff) * 2);
                u32 bf[4];
                ldsm_x4(bf, addr);
                if (kt == 0) {
                    mma16816_h_dc(sa[2 * p],     aQ[0], bf[0], bf[1]);
                    mma16816_h_dc(sa[2 * p + 1], aQ[0], bf[2], bf[3]);
                } else {
                    mma16816_h(sa[2 * p],     aQ[1], bf[0], bf[1]);
                    mma16816_h(sa[2 * p + 1], aQ[1], bf[2], bf[3]);
                }
            }
        }

        // ---- exp_a ----------------------------------------------------------
#pragma unroll
        for (int nt = 0; nt < 8; nt++) {
            sa[nt][0] = ex2_h2(sa[nt][0]);
            sa[nt][1] = ex2_h2(sa[nt][1]);
        }

        // ---- S_b: j 64..127 (p 4..7) ---------------------------------------
#pragma unroll
        for (int kt = 0; kt < 2; kt++) {
            int coff = kt * 16 + (lm & 1) * 8;
#pragma unroll
            for (int p = 0; p < 4; p++) {
                int ntb = 2 * (p + 4) + (lm >> 1);
                u32 addr = sbase + (u32)((kb + (ntb * 8 + lrow) * KPITCH + coff) * 2);
                u32 bf[4];
                ldsm_x4(bf, addr);
                if (kt == 0) {
                    mma16816_h_dc(sb16[2 * p],     aQ[0], bf[0], bf[1]);
                    mma16816_h_dc(sb16[2 * p + 1], aQ[0], bf[2], bf[3]);
                } else {
                    mma16816_h(sb16[2 * p],     aQ[1], bf[0], bf[1]);
                    mma16816_h(sb16[2 * p + 1], aQ[1], bf[2], bf[3]);
                }
            }
        }

        // ---- PV_a: kt 0..3 consume sa --------------------------------------
#pragma unroll
        for (int kt = 0; kt < 4; kt++) {
            const unsigned* aP = &sa[2 * kt][0];
            int coff = kt * 16 + (lm & 1) * 8;
#pragma unroll
            for (int p = 0; p < 2; p++) {
                int ntb = 2 * p + (lm >> 1);
                u32 addr = sbase + (u32)((vb + (ntb * 8 + lrow) * VPITCH + coff) * 2);
                u32 bf[4];
                ldsm_x4(bf, addr);
                if (kt == 0) {
                    mma16816_h_dc(o16[2 * p],     aP, bf[0], bf[1]);
                    mma16816_h_dc(o16[2 * p + 1], aP, bf[2], bf[3]);
                } else {
                    mma16816_h(o16[2 * p],     aP, bf[0], bf[1]);
                    mma16816_h(o16[2 * p + 1], aP, bf[2], bf[3]);
                }
            }
            if (kt == 0) mma16816_h_dc(L16, aP, vone, vone);
            else         mma16816_h(L16, aP, vone, vone);
        }

        // ---- exp_b ----------------------------------------------------------
#pragma unroll
        for (int nt = 0; nt < 8; nt++) {
            sb16[nt][0] = ex2_h2(sb16[nt][0]);
            sb16[nt][1] = ex2_h2(sb16[nt][1]);
        }

        // ---- PV_b: kt 4..7 consume sb16 ------------------------------------
#pragma unroll
        for (int kt = 4; kt < 8; kt++) {
            const unsigned* aP = &sb16[2 * (kt - 4)][0];
            int coff = kt * 16 + (lm & 1) * 8;
#pragma unroll
            for (int p = 0; p < 2; p++) {
                int ntb = 2 * p + (lm >> 1);
                u32 addr = sbase + (u32)((vb + (ntb * 8 + lrow) * VPITCH + coff) * 2);
                u32 bf[4];
                ldsm_x4(bf, addr);
                mma16816_h(o16[2 * p],     aP, bf[0], bf[1]);
                mma16816_h(o16[2 * p + 1], aP, bf[2], bf[3]);
            }
            mma16816_h(L16, aP, vone, vone);
        }

        // ---- flush per-tile fp16 accumulators into fp32 --------------------
#pragma unroll
        for (int nt = 0; nt < 4; nt++) {
            float2 f0 = __half22float2(*reinterpret_cast<__half2*>(&o16[nt][0]));
            float2 f1 = __half22float2(*reinterpret_cast<__half2*>(&o16[nt][1]));
            o[nt][0] += f0.x; o[nt][1] += f0.y;
            o[nt][2] += f1.x; o[nt][3] += f1.y;
        }
        L0 += __low2float(*reinterpret_cast<__half2*>(&L16[0]));
        L1 += __low2float(*reinterpret_cast<__half2*>(&L16[1]));
    }

    // ---- L valid in lr==0 lanes; broadcast within quad ---------------------
    L0 = __shfl_sync(FULL, L0, lane & 28);
    L1 = __shfl_sync(FULL, L1, lane & 28);
    float inv0 = 1.0f / L0, inv1 = 1.0f / L1;

    // ---- epilogue: normalize, stage, write hi|lo rows into g_o2 ------------
    __syncthreads();
    {
        int r0 = wid * 16 + lq;
#pragma unroll
        for (int nt = 0; nt < 4; nt++) {
            int d = nt * 8 + lr * 2;
            SMf[r0 * 33 + d]           = o[nt][0] * inv0;
            SMf[r0 * 33 + d + 1]       = o[nt][1] * inv0;
            SMf[(r0 + 8) * 33 + d]     = o[nt][2] * inv1;
            SMf[(r0 + 8) * 33 + d + 1] = o[nt][3] * inv1;
        }
    }
    __syncthreads();
#pragma unroll
    for (int t = 0; t < 16; t++) {
        int idx = tid + t * 256;
        int i = idx >> 5, d = idx & 31;
        float v = SMf[i * 33 + d];
        __half hh = __float2half_rn(v);
        __half* rowp = g_o2 + ((size_t)(b * N_ + i0 + i)) * 256 + h * DHEAD_ + d;
        rowp[0]   = hh;
        rowp[128] = __float2half_rn(v - __half2float(hh));
    }
}

// ---------------------------------------------------------------------------
extern "C" void kernel_launch(void* const* d_in, const int* in_sizes, int n_in,
                              void* d_out, int out_size) {
    const float* x     = (const float*)d_in[0];
    const float* g     = (const float*)d_in[1];
    const float* beta  = (const float*)d_in[2];
    const float* w_qkv = (const float*)d_in[3];
    const float* w_out = (const float*)d_in[4];
    const float* b_out = (const float*)d_in[5];
    float* out = (float*)d_out;

    w_convert_kernel<<<OQKV_ + HID_, 128>>>(w_qkv, w_out);

    dim3 gx(N_ / 32, B_);
    x_convert_kernel<<<gx, 256>>>(x, g, beta);

    dim3 gq(N_ / 64, 3, B_);
    tc_gemm_kernel<<<gq, 256>>>(nullptr, nullptr, 0);

    dim3 ga(N_ / 128, B_ * HEADS_);
    attn_mma_kernel<<<ga, 256>>>();

    dim3 go(N_ / 64, 1, B_);
    tc_gemm_kernel<<<go, 256>>>(out, b_out, 3);
}